// round 13
// baseline (speedup 1.0000x reference)
#include <cuda_runtime.h>
#include <cstdint>
#include <cstddef>

// ============================================================================
// MLP_SAT v5: barrier-free direct-to-fragment design.
//   K-permutation: channel(tile c, step s, q) = 16c + 4*(q&3) + 2s + (q>>2)
//   so each thread's A fragment = contiguous float4 of the source row.
//   W1/W2 pre-packed with the same permutation (prep_kernel).
//   gemm_LC: no smem, no bars. edge_kernel: one block bar total; 4 CTAs/SM.
// ============================================================================

#define NLITS 131072
#define NCLS  65536

__device__ float g_L[(size_t)NLITS * 256];
__device__ float g_C[(size_t)NCLS * 256];
__device__ float g_sums[NCLS];
__device__ float g_cnts[NCLS];
__device__ unsigned g_W1p[196608];  // [h][K<48][n<256][t4][th], permuted
__device__ unsigned g_W2p[16384];   // [K<32][n<64][t4][th], permuted
__device__ unsigned g_W3p[1536];    // standard k-pair pack (layer3 A from smem)

__device__ __forceinline__ unsigned f2tf(float x) {
    unsigned r;
    asm("cvt.rna.tf32.f32 %0, %1;" : "=r"(r) : "f"(x));
    return r;
}

__device__ __forceinline__ void mma_tf32(float* d, const unsigned* a, const unsigned* b) {
    asm volatile(
        "mma.sync.aligned.m16n8k8.row.col.f32.tf32.tf32.f32 "
        "{%0,%1,%2,%3}, {%4,%5,%6,%7}, {%8,%9}, {%0,%1,%2,%3};\n"
        : "+f"(d[0]), "+f"(d[1]), "+f"(d[2]), "+f"(d[3])
        : "r"(a[0]), "r"(a[1]), "r"(a[2]), "r"(a[3]), "r"(b[0]), "r"(b[1]));
}

// ----------------------------------------------------------------------------
// One-time weight repack.
// Permuted (W1, W2): k -> (c = k>>4, r = k&15); t4 = r>>2, s = (r>>1)&1,
// th = r&1, K = 2c+s.  P[((K*N + n)*4 + t4)*2 + th] = W[k][n].
// Standard (W3):      k8 = k>>3, t4 = k&3, th = (k>>2)&1.
// ----------------------------------------------------------------------------
__global__ void prep_kernel(const float* __restrict__ W1,
                            const float* __restrict__ W2,
                            const float* __restrict__ W3) {
    int idx = blockIdx.x * blockDim.x + threadIdx.x;
    if (idx < 196608) {                       // W1: 768 x 256
        int n = idx & 255, k = idx >> 8;
        int h = (k >= 384) ? 1 : 0;
        int kl = k - h * 384;
        int c = kl >> 4, r = kl & 15;
        int t4 = r >> 2, s = (r >> 1) & 1, th = r & 1;
        int K = 2 * c + s;
        g_W1p[(((h * 48 + K) * 256 + n) * 4 + t4) * 2 + th] = f2tf(W1[k * 256 + n]);
    }
    if (idx < 16384) {                        // W2: 256 x 64
        int k = idx >> 6, n = idx & 63;
        int c = k >> 4, r = k & 15;
        int t4 = r >> 2, s = (r >> 1) & 1, th = r & 1;
        int K = 2 * c + s;
        g_W2p[((K * 64 + n) * 4 + t4) * 2 + th] = f2tf(W2[k * 64 + n]);
    }
    if (idx < 1536) {                         // W3: 64 x 20 (pad 24), standard
        int th = idx & 1, t4 = (idx >> 1) & 3, r = idx >> 3;  // r = k8*24+n
        int k8 = r / 24, n = r % 24;
        int k = k8 * 8 + th * 4 + t4;
        g_W3p[idx] = f2tf((n < 20) ? W3[k * 20 + n] : 0.f);
    }
}

// ----------------------------------------------------------------------------
// Merged GEMM, barrier-free: rows [0,nL) -> g_L (+b1); [nL,nL+nC) -> g_C.
// BM=128, BN=128 (grid.y=2). 8 warps = 4(m) x 2(n); warp tile 32x64.
// A fragments loaded directly (permuted float4), B from g_W1p.
// ----------------------------------------------------------------------------
__global__ __launch_bounds__(256, 2) void gemm_LC(
    const float* __restrict__ l_embs, const float* __restrict__ c_embs,
    const float* __restrict__ b1, int nL)
{
    const int tid  = threadIdx.x;
    const int warp = tid >> 5, lane = tid & 31;
    const int g = lane >> 2, t4 = lane & 3;
    const int wm = warp & 3, wn = warp >> 2;
    const int rowBase = blockIdx.x * 128;
    const int colBase = blockIdx.y * 128;

    const bool isL = rowBase < nL;
    const float* __restrict__ A = isL ? l_embs + (size_t)rowBase * 384
                                      : c_embs + (size_t)(rowBase - nL) * 384;
    const unsigned* __restrict__ Wp = g_W1p + (isL ? 0 : 98304);
    float* __restrict__ out = isL ? g_L + (size_t)rowBase * 256
                                  : g_C + (size_t)(rowBase - nL) * 256;

    const int rb = wm * 32;
    // 4 A-rows this thread feeds: rb+g, rb+g+8 (mi=0); rb+16+g, rb+24+g (mi=1)
    const size_t r0 = (size_t)(rb + g     ) * 384;
    const size_t r1 = (size_t)(rb + g +  8) * 384;
    const size_t r2 = (size_t)(rb + g + 16) * 384;
    const size_t r3 = (size_t)(rb + g + 24) * 384;

    float acc[2][8][4];
    #pragma unroll
    for (int mi = 0; mi < 2; mi++)
        #pragma unroll
        for (int ni = 0; ni < 8; ni++)
            #pragma unroll
            for (int q = 0; q < 4; q++) acc[mi][ni][q] = 0.f;

    for (int c = 0; c < 24; c++) {
        const int ko = c * 16 + t4 * 4;
        float4 f0 = *(const float4*)&A[r0 + ko];
        float4 f1 = *(const float4*)&A[r1 + ko];
        float4 f2 = *(const float4*)&A[r2 + ko];
        float4 f3 = *(const float4*)&A[r3 + ko];
        unsigned u0[4] = {f2tf(f0.x), f2tf(f0.y), f2tf(f0.z), f2tf(f0.w)};
        unsigned u1[4] = {f2tf(f1.x), f2tf(f1.y), f2tf(f1.z), f2tf(f1.w)};
        unsigned u2[4] = {f2tf(f2.x), f2tf(f2.y), f2tf(f2.z), f2tf(f2.w)};
        unsigned u3[4] = {f2tf(f3.x), f2tf(f3.y), f2tf(f3.z), f2tf(f3.w)};

        #pragma unroll
        for (int s = 0; s < 2; s++) {
            const int K = 2 * c + s;
            unsigned a0[4] = {u0[2*s], u1[2*s], u0[2*s+1], u1[2*s+1]};
            unsigned a1[4] = {u2[2*s], u3[2*s], u2[2*s+1], u3[2*s+1]};
            #pragma unroll
            for (int ni = 0; ni < 8; ni++) {
                int col = colBase + wn * 64 + ni * 8 + g;
                uint2 bp = *(const uint2*)&Wp[((size_t)(K * 256 + col) * 4 + t4) * 2];
                unsigned b[2] = {bp.x, bp.y};
                mma_tf32(acc[0][ni], a0, b);
                mma_tf32(acc[1][ni], a1, b);
            }
        }
    }

    #pragma unroll
    for (int mi = 0; mi < 2; mi++) {
        #pragma unroll
        for (int ni = 0; ni < 8; ni++) {
            int rr = rb + mi * 16 + g;
            int c0 = colBase + wn * 64 + ni * 8 + t4 * 2;
            float bb0 = isL ? b1[c0]     : 0.f;
            float bb1 = isL ? b1[c0 + 1] : 0.f;
            float2 v0 = {acc[mi][ni][0] + bb0, acc[mi][ni][1] + bb1};
            float2 v1 = {acc[mi][ni][2] + bb0, acc[mi][ni][3] + bb1};
            *(float2*)&out[(size_t)rr * 256 + c0] = v0;
            *(float2*)&out[(size_t)(rr + 8) * 256 + c0] = v1;
        }
    }
}

// ----------------------------------------------------------------------------
__global__ void zero_kernel(int n) {
    int i = blockIdx.x * blockDim.x + threadIdx.x;
    if (i < n) { g_sums[i] = 0.f; g_cnts[i] = 0.f; }
}

// ----------------------------------------------------------------------------
// Edge kernel v5: 128 edges/block, 8 warps x 16 edges, 4 CTAs/SM.
// Layer 2 fully barrier-free: per chunk 4 LDG.128 (L/C rows), relu/cvt in
// regs, mma with B direct from g_W2p. h2 rows are warp-private -> syncwarp.
// One block barrier before layer 4.
// ----------------------------------------------------------------------------
#define EK_SMEM_WORDS (128*68 + 64 + 24 + 20 + 4 + 256)
#define EK_SMEM_BYTES (EK_SMEM_WORDS * 4)

__global__ __launch_bounds__(256, 4) void edge_kernel(
    const int* __restrict__ edge_i, const int* __restrict__ edge_j,
    const float* __restrict__ b2, const float* __restrict__ b3,
    const float* __restrict__ W4, const float* __restrict__ b4,
    int nE)
{
    extern __shared__ unsigned smu[];
    unsigned* h2 = smu;                     // [128][68]
    float* b2s = (float*)(h2 + 128 * 68);   // 64
    float* b3s = b2s + 64;                  // 24
    float* W4s = b3s + 24;                  // 20
    float* b4s = W4s + 20;                  // 4
    int*   eis = (int*)(b4s + 4);           // 128
    int*   ejs = eis + 128;                 // 128
    float* h3f = (float*)h2;                // h3 overlays h2 rows (stride 68)

    const int tid  = threadIdx.x;
    const int warp = tid >> 5, lane = tid & 31;
    const int g = lane >> 2, t4 = lane & 3;
    const int ebase = blockIdx.x * 128;

    if (tid < 64) b2s[tid] = b2[tid];
    if (tid < 24) b3s[tid] = (tid < 20) ? b3[tid] : 0.f;
    if (tid < 20) W4s[tid] = W4[tid];
    if (tid == 0) b4s[0] = b4[0];
    if (tid < 128) {
        int ge = ebase + tid;
        eis[tid] = (ge < nE) ? edge_i[ge] : 0;
        ejs[tid] = (ge < nE) ? edge_j[ge] : 0;
    }
    __syncthreads();

    // ---- layer 2: warp-private, barrier-free ----
    const int ew = warp * 16;               // warp's 16 edges
    const size_t rL0 = (size_t)eis[ew + g    ] * 256;
    const size_t rL1 = (size_t)eis[ew + g + 8] * 256;
    const size_t rC0 = (size_t)ejs[ew + g    ] * 256;
    const size_t rC1 = (size_t)ejs[ew + g + 8] * 256;

    float acc[8][4];
    #pragma unroll
    for (int ni = 0; ni < 8; ni++)
        #pragma unroll
        for (int q = 0; q < 4; q++) acc[ni][q] = 0.f;

    for (int c = 0; c < 16; c++) {
        const int ko = c * 16 + t4 * 4;
        float4 l0 = *(const float4*)&g_L[rL0 + ko];
        float4 l1 = *(const float4*)&g_L[rL1 + ko];
        float4 c0 = *(const float4*)&g_C[rC0 + ko];
        float4 c1 = *(const float4*)&g_C[rC1 + ko];
        unsigned h0[4], h1[4];
        h0[0] = f2tf(fmaxf(l0.x + c0.x, 0.f));
        h0[1] = f2tf(fmaxf(l0.y + c0.y, 0.f));
        h0[2] = f2tf(fmaxf(l0.z + c0.z, 0.f));
        h0[3] = f2tf(fmaxf(l0.w + c0.w, 0.f));
        h1[0] = f2tf(fmaxf(l1.x + c1.x, 0.f));
        h1[1] = f2tf(fmaxf(l1.y + c1.y, 0.f));
        h1[2] = f2tf(fmaxf(l1.z + c1.z, 0.f));
        h1[3] = f2tf(fmaxf(l1.w + c1.w, 0.f));

        #pragma unroll
        for (int s = 0; s < 2; s++) {
            const int K = 2 * c + s;
            unsigned a[4] = {h0[2*s], h1[2*s], h0[2*s+1], h1[2*s+1]};
            #pragma unroll
            for (int ni = 0; ni < 8; ni++) {
                int col = ni * 8 + g;
                uint2 bp = *(const uint2*)&g_W2p[((K * 64 + col) * 4 + t4) * 2];
                unsigned b[2] = {bp.x, bp.y};
                mma_tf32(acc[ni], a, b);
            }
        }
    }

    // ---- layer-2 epilogue: h2 = relu(acc + b2), rows warp-private ----
    #pragma unroll
    for (int ni = 0; ni < 8; ni++) {
        int col = ni * 8 + t4 * 2;
        float bb0 = b2s[col], bb1 = b2s[col + 1];
        h2[(ew + g    ) * 68 + col    ] = f2tf(fmaxf(acc[ni][0] + bb0, 0.f));
        h2[(ew + g    ) * 68 + col + 1] = f2tf(fmaxf(acc[ni][1] + bb1, 0.f));
        h2[(ew + g + 8) * 68 + col    ] = f2tf(fmaxf(acc[ni][2] + bb0, 0.f));
        h2[(ew + g + 8) * 68 + col + 1] = f2tf(fmaxf(acc[ni][3] + bb1, 0.f));
    }
    __syncwarp();

    // ---- layer 3: warp reads ONLY its own 16 h2 rows; standard pack ----
    {
        float a3[3][4];
        #pragma unroll
        for (int ni = 0; ni < 3; ni++)
            #pragma unroll
            for (int q = 0; q < 4; q++) a3[ni][q] = 0.f;

        #pragma unroll
        for (int k8 = 0; k8 < 8; k8++) {
            const int kc = k8 * 8;
            unsigned a[4];
            a[0] = h2[(ew + g    ) * 68 + kc + t4    ];
            a[1] = h2[(ew + g + 8) * 68 + kc + t4    ];
            a[2] = h2[(ew + g    ) * 68 + kc + t4 + 4];
            a[3] = h2[(ew + g + 8) * 68 + kc + t4 + 4];
            #pragma unroll
            for (int ni = 0; ni < 3; ni++) {
                int col = ni * 8 + g;
                uint2 bp = *(const uint2*)&g_W3p[((k8 * 24 + col) * 4 + t4) * 2];
                unsigned b[2] = {bp.x, bp.y};
                mma_tf32(a3[ni], a, b);
            }
        }
        // h3 overlays h2 rows (warp-private; all reads above precede stores)
        #pragma unroll
        for (int ni = 0; ni < 3; ni++) {
            int col = ni * 8 + t4 * 2;
            float bb0 = b3s[col], bb1 = b3s[col + 1];
            h3f[(ew + g    ) * 68 + col    ] = fmaxf(a3[ni][0] + bb0, 0.f);
            h3f[(ew + g    ) * 68 + col + 1] = fmaxf(a3[ni][1] + bb1, 0.f);
            h3f[(ew + g + 8) * 68 + col    ] = fmaxf(a3[ni][2] + bb0, 0.f);
            h3f[(ew + g + 8) * 68 + col + 1] = fmaxf(a3[ni][3] + bb1, 0.f);
        }
    }
    __syncthreads();   // the only block barrier after staging

    // ---- layer 4 + per-clause atomic accumulation ----
    if (tid < 128) {
        int ge = ebase + tid;
        if (ge < nE) {
            float w = b4s[0];
            #pragma unroll
            for (int j = 0; j < 20; j++) w += h3f[tid * 68 + j] * W4s[j];
            int cl = ejs[tid];
            atomicAdd(&g_sums[cl], w);
            atomicAdd(&g_cnts[cl], 1.0f);
        }
    }
}

// ----------------------------------------------------------------------------
__global__ void finalize_kernel(const int* __restrict__ edge_j,
                                float* __restrict__ out, int nE) {
    int e = blockIdx.x * blockDim.x + threadIdx.x;
    if (e < nE) {
        int j = edge_j[e];
        out[e] = g_sums[j] / fmaxf(g_cnts[j], 1.0f);
    }
}

// ----------------------------------------------------------------------------
extern "C" void kernel_launch(void* const* d_in, const int* in_sizes, int n_in,
                              void* d_out, int out_size)
{
    const float* l_embs = (const float*)d_in[0];
    const float* c_embs = (const float*)d_in[1];
    const int*   edge_i = (const int*)d_in[2];
    const int*   edge_j = (const int*)d_in[3];
    const float* W1     = (const float*)d_in[4];
    const float* b1     = (const float*)d_in[5];
    const float* W2     = (const float*)d_in[6];
    const float* b2     = (const float*)d_in[7];
    const float* W3     = (const float*)d_in[8];
    const float* b3     = (const float*)d_in[9];
    const float* W4     = (const float*)d_in[10];
    const float* b4     = (const float*)d_in[11];
    float* out = (float*)d_out;

    const int nL = in_sizes[0] / 384;   // 131072
    const int nC = in_sizes[1] / 384;   // 65536
    const int nE = in_sizes[2];         // 524288

    cudaFuncSetAttribute(edge_kernel,
                         cudaFuncAttributeMaxDynamicSharedMemorySize,
                         EK_SMEM_BYTES);

    prep_kernel<<<768, 256>>>(W1, W2, W3);
    gemm_LC<<<dim3((nL + nC) / 128, 2), 256>>>(l_embs, c_embs, b1, nL);
    zero_kernel<<<(nC + 255) / 256, 256>>>(nC);
    edge_kernel<<<(nE + 127) / 128, 256, EK_SMEM_BYTES>>>(
        edge_i, edge_j, b2, b3, W4, b4, nE);
    finalize_kernel<<<(nE + 255) / 256, 256>>>(edge_j, out, nE);
}

// round 15
// speedup vs baseline: 1.1777x; 1.1777x over previous
#include <cuda_runtime.h>
#include <cstdint>
#include <cstddef>

// ============================================================================
// MLP_SAT v6.1: v5 edge kernel (barrier-free, 4 CTAs/SM) + cp.async-pipelined
// GEMM. v6.1 fixes the pipeline protocol: wait_group 0 BEFORE touching the
// stage (v6's wait_group 1 before issuing the next stage never actually
// waited — 1 group pending == the stage being read).
// ============================================================================

#define NLITS 131072
#define NCLS  65536

__device__ float g_L[(size_t)NLITS * 256];
__device__ float g_C[(size_t)NCLS * 256];
__device__ float g_sums[NCLS];
__device__ float g_cnts[NCLS];
__device__ unsigned g_W1p[196608];  // [h][k8<48][n<256][t4][th] standard
__device__ unsigned g_W2p[16384];   // [K<32][n<64][t4][th] permuted
__device__ unsigned g_W3p[1536];    // [k8<8][n<24][t4][th] standard

__device__ __forceinline__ unsigned f2tf(float x) {
    unsigned r;
    asm("cvt.rna.tf32.f32 %0, %1;" : "=r"(r) : "f"(x));
    return r;
}

__device__ __forceinline__ void mma_tf32(float* d, const unsigned* a, const unsigned* b) {
    asm volatile(
        "mma.sync.aligned.m16n8k8.row.col.f32.tf32.tf32.f32 "
        "{%0,%1,%2,%3}, {%4,%5,%6,%7}, {%8,%9}, {%0,%1,%2,%3};\n"
        : "+f"(d[0]), "+f"(d[1]), "+f"(d[2]), "+f"(d[3])
        : "r"(a[0]), "r"(a[1]), "r"(a[2]), "r"(a[3]), "r"(b[0]), "r"(b[1]));
}

__device__ __forceinline__ void cp_async16(unsigned smem_addr, const void* gptr) {
    asm volatile("cp.async.cg.shared.global [%0], [%1], 16;\n"
                 :: "r"(smem_addr), "l"(gptr));
}
__device__ __forceinline__ void cp_commit() {
    asm volatile("cp.async.commit_group;\n");
}
template<int N>
__device__ __forceinline__ void cp_wait() {
    asm volatile("cp.async.wait_group %0;\n" :: "n"(N));
}

// ----------------------------------------------------------------------------
// One-time weight repack.
// ----------------------------------------------------------------------------
__global__ void prep_kernel(const float* __restrict__ W1,
                            const float* __restrict__ W2,
                            const float* __restrict__ W3) {
    int idx = blockIdx.x * blockDim.x + threadIdx.x;
    if (idx < 196608) {                       // W1: standard k-pair pack
        int n = idx & 255, k = idx >> 8;
        int h = (k >= 384) ? 1 : 0;
        int kl = k - h * 384;
        int k8 = kl >> 3, t4 = kl & 3, th = (kl >> 2) & 1;
        g_W1p[(((h * 48 + k8) * 256 + n) * 4 + t4) * 2 + th] = f2tf(W1[k * 256 + n]);
    }
    if (idx < 16384) {                        // W2: permuted pack (edge v5)
        int k = idx >> 6, n = idx & 63;
        int c = k >> 4, r = k & 15;
        int t4 = r >> 2, s = (r >> 1) & 1, th = r & 1;
        int K = 2 * c + s;
        g_W2p[((K * 64 + n) * 4 + t4) * 2 + th] = f2tf(W2[k * 64 + n]);
    }
    if (idx < 1536) {                         // W3: standard, n padded to 24
        int th = idx & 1, t4 = (idx >> 1) & 3, r = idx >> 3;  // r = k8*24+n
        int k8 = r / 24, n = r % 24;
        int k = k8 * 8 + th * 4 + t4;
        g_W3p[idx] = f2tf((n < 20) ? W3[k * 20 + n] : 0.f);
    }
}

// ----------------------------------------------------------------------------
// Merged GEMM v6.1: BM=128, BN=128, BK=32; cp.async double-buffered A tiles;
// B fragments direct LDG from g_W1p. One __syncthreads per kt.
// Protocol per kt: wait_group 0 (stage kt landed) -> bar (all warps done
// with the other buffer) -> issue kt+1 -> mma(kt).
// ----------------------------------------------------------------------------
__global__ __launch_bounds__(256, 2) void gemm_LC(
    const float* __restrict__ l_embs, const float* __restrict__ c_embs,
    const float* __restrict__ b1, int nL)
{
    __shared__ float As[2][128 * 36];

    const int tid  = threadIdx.x;
    const int warp = tid >> 5, lane = tid & 31;
    const int g = lane >> 2, t4 = lane & 3;
    const int wm = warp & 3, wn = warp >> 2;
    const int rowBase = blockIdx.x * 128;
    const int colBase = blockIdx.y * 128;

    const bool isL = rowBase < nL;
    const float* __restrict__ A = isL ? l_embs + (size_t)rowBase * 384
                                      : c_embs + (size_t)(rowBase - nL) * 384;
    const unsigned* __restrict__ Wp = g_W1p + (isL ? 0 : 98304);
    float* __restrict__ out = isL ? g_L + (size_t)rowBase * 256
                                  : g_C + (size_t)(rowBase - nL) * 256;

    // per-thread cp.async coords: 4 slots of (row, col4)
    const int r_[4] = { tid >> 3, (tid + 256) >> 3, (tid + 512) >> 3, (tid + 768) >> 3 };
    const int c_    = (tid & 7) * 4;

    float acc[2][8][4];
    #pragma unroll
    for (int mi = 0; mi < 2; mi++)
        #pragma unroll
        for (int ni = 0; ni < 8; ni++)
            #pragma unroll
            for (int q = 0; q < 4; q++) acc[mi][ni][q] = 0.f;

    // issue stage 0
    #pragma unroll
    for (int s = 0; s < 4; s++) {
        unsigned dst = (unsigned)__cvta_generic_to_shared(&As[0][r_[s] * 36 + c_]);
        cp_async16(dst, &A[(size_t)r_[s] * 384 + c_]);
    }
    cp_commit();

    for (int kt = 0; kt < 12; kt++) {
        const int st = kt & 1;
        cp_wait<0>();      // stage kt fully landed (all committed groups done)
        __syncthreads();   // visible to all; all warps done with buffer st^1

        if (kt < 11) {     // issue stage kt+1 into the other buffer (overlaps mma)
            const int ko = (kt + 1) * 32;
            #pragma unroll
            for (int s = 0; s < 4; s++) {
                unsigned dst = (unsigned)__cvta_generic_to_shared(&As[st ^ 1][r_[s] * 36 + c_]);
                cp_async16(dst, &A[(size_t)r_[s] * 384 + ko + c_]);
            }
            cp_commit();
        }

        #pragma unroll
        for (int k8 = 0; k8 < 4; k8++) {
            const int kc = k8 * 8;
            const int k8g = kt * 4 + k8;
            unsigned afr[2][4];
            #pragma unroll
            for (int mi = 0; mi < 2; mi++) {
                int rb = wm * 32 + mi * 16;
                afr[mi][0] = f2tf(As[st][(rb + g    ) * 36 + kc + t4    ]);
                afr[mi][1] = f2tf(As[st][(rb + g + 8) * 36 + kc + t4    ]);
                afr[mi][2] = f2tf(As[st][(rb + g    ) * 36 + kc + t4 + 4]);
                afr[mi][3] = f2tf(As[st][(rb + g + 8) * 36 + kc + t4 + 4]);
            }
            #pragma unroll
            for (int ni = 0; ni < 8; ni++) {
                int col = colBase + wn * 64 + ni * 8 + g;
                uint2 bp = *(const uint2*)&Wp[((size_t)(k8g * 256 + col) * 4 + t4) * 2];
                unsigned b[2] = {bp.x, bp.y};
                mma_tf32(acc[0][ni], afr[0], b);
                mma_tf32(acc[1][ni], afr[1], b);
            }
        }
    }

    #pragma unroll
    for (int mi = 0; mi < 2; mi++) {
        #pragma unroll
        for (int ni = 0; ni < 8; ni++) {
            int rr = wm * 32 + mi * 16 + g;
            int c0 = colBase + wn * 64 + ni * 8 + t4 * 2;
            float bb0 = isL ? b1[c0]     : 0.f;
            float bb1 = isL ? b1[c0 + 1] : 0.f;
            float2 v0 = {acc[mi][ni][0] + bb0, acc[mi][ni][1] + bb1};
            float2 v1 = {acc[mi][ni][2] + bb0, acc[mi][ni][3] + bb1};
            *(float2*)&out[(size_t)rr * 256 + c0] = v0;
            *(float2*)&out[(size_t)(rr + 8) * 256 + c0] = v1;
        }
    }
}

// ----------------------------------------------------------------------------
__global__ void zero_kernel(int n) {
    int i = blockIdx.x * blockDim.x + threadIdx.x;
    if (i < n) { g_sums[i] = 0.f; g_cnts[i] = 0.f; }
}

// ----------------------------------------------------------------------------
// Edge kernel v5 (unchanged): 128 edges/block, 8 warps x 16 edges, 4 CTAs/SM.
// ----------------------------------------------------------------------------
#define EK_SMEM_WORDS (128*68 + 64 + 24 + 20 + 4 + 256)
#define EK_SMEM_BYTES (EK_SMEM_WORDS * 4)

__global__ __launch_bounds__(256, 4) void edge_kernel(
    const int* __restrict__ edge_i, const int* __restrict__ edge_j,
    const float* __restrict__ b2, const float* __restrict__ b3,
    const float* __restrict__ W4, const float* __restrict__ b4,
    int nE)
{
    extern __shared__ unsigned smu[];
    unsigned* h2 = smu;                     // [128][68]
    float* b2s = (float*)(h2 + 128 * 68);   // 64
    float* b3s = b2s + 64;                  // 24
    float* W4s = b3s + 24;                  // 20
    float* b4s = W4s + 20;                  // 4
    int*   eis = (int*)(b4s + 4);           // 128
    int*   ejs = eis + 128;                 // 128
    float* h3f = (float*)h2;                // h3 overlays h2 rows (stride 68)

    const int tid  = threadIdx.x;
    const int warp = tid >> 5, lane = tid & 31;
    const int g = lane >> 2, t4 = lane & 3;
    const int ebase = blockIdx.x * 128;

    if (tid < 64) b2s[tid] = b2[tid];
    if (tid < 24) b3s[tid] = (tid < 20) ? b3[tid] : 0.f;
    if (tid < 20) W4s[tid] = W4[tid];
    if (tid == 0) b4s[0] = b4[0];
    if (tid < 128) {
        int ge = ebase + tid;
        eis[tid] = (ge < nE) ? edge_i[ge] : 0;
        ejs[tid] = (ge < nE) ? edge_j[ge] : 0;
    }
    __syncthreads();

    // ---- layer 2: warp-private, barrier-free ----
    const int ew = warp * 16;
    const size_t rL0 = (size_t)eis[ew + g    ] * 256;
    const size_t rL1 = (size_t)eis[ew + g + 8] * 256;
    const size_t rC0 = (size_t)ejs[ew + g    ] * 256;
    const size_t rC1 = (size_t)ejs[ew + g + 8] * 256;

    float acc[8][4];
    #pragma unroll
    for (int ni = 0; ni < 8; ni++)
        #pragma unroll
        for (int q = 0; q < 4; q++) acc[ni][q] = 0.f;

    for (int c = 0; c < 16; c++) {
        const int ko = c * 16 + t4 * 4;
        float4 l0 = *(const float4*)&g_L[rL0 + ko];
        float4 l1 = *(const float4*)&g_L[rL1 + ko];
        float4 c0 = *(const float4*)&g_C[rC0 + ko];
        float4 c1 = *(const float4*)&g_C[rC1 + ko];
        unsigned h0[4], h1[4];
        h0[0] = f2tf(fmaxf(l0.x + c0.x, 0.f));
        h0[1] = f2tf(fmaxf(l0.y + c0.y, 0.f));
        h0[2] = f2tf(fmaxf(l0.z + c0.z, 0.f));
        h0[3] = f2tf(fmaxf(l0.w + c0.w, 0.f));
        h1[0] = f2tf(fmaxf(l1.x + c1.x, 0.f));
        h1[1] = f2tf(fmaxf(l1.y + c1.y, 0.f));
        h1[2] = f2tf(fmaxf(l1.z + c1.z, 0.f));
        h1[3] = f2tf(fmaxf(l1.w + c1.w, 0.f));

        #pragma unroll
        for (int s = 0; s < 2; s++) {
            const int K = 2 * c + s;
            unsigned a[4] = {h0[2*s], h1[2*s], h0[2*s+1], h1[2*s+1]};
            #pragma unroll
            for (int ni = 0; ni < 8; ni++) {
                int col = ni * 8 + g;
                uint2 bp = *(const uint2*)&g_W2p[((K * 64 + col) * 4 + t4) * 2];
                unsigned b[2] = {bp.x, bp.y};
                mma_tf32(acc[ni], a, b);
            }
        }
    }

    // ---- layer-2 epilogue ----
    #pragma unroll
    for (int ni = 0; ni < 8; ni++) {
        int col = ni * 8 + t4 * 2;
        float bb0 = b2s[col], bb1 = b2s[col + 1];
        h2[(ew + g    ) * 68 + col    ] = f2tf(fmaxf(acc[ni][0] + bb0, 0.f));
        h2[(ew + g    ) * 68 + col + 1] = f2tf(fmaxf(acc[ni][1] + bb1, 0.f));
        h2[(ew + g + 8) * 68 + col    ] = f2tf(fmaxf(acc[ni][2] + bb0, 0.f));
        h2[(ew + g + 8) * 68 + col + 1] = f2tf(fmaxf(acc[ni][3] + bb1, 0.f));
    }
    __syncwarp();

    // ---- layer 3 ----
    {
        float a3[3][4];
        #pragma unroll
        for (int ni = 0; ni < 3; ni++)
            #pragma unroll
            for (int q = 0; q < 4; q++) a3[ni][q] = 0.f;

        #pragma unroll
        for (int k8 = 0; k8 < 8; k8++) {
            const int kc = k8 * 8;
            unsigned a[4];
            a[0] = h2[(ew + g    ) * 68 + kc + t4    ];
            a[1] = h2[(ew + g + 8) * 68 + kc + t4    ];
            a[2] = h2[(ew + g    ) * 68 + kc + t4 + 4];
            a[3] = h2[(ew + g + 8) * 68 + kc + t4 + 4];
            #pragma unroll
            for (int ni = 0; ni < 3; ni++) {
                int col = ni * 8 + g;
                uint2 bp = *(const uint2*)&g_W3p[((k8 * 24 + col) * 4 + t4) * 2];
                unsigned b[2] = {bp.x, bp.y};
                mma_tf32(a3[ni], a, b);
            }
        }
        #pragma unroll
        for (int ni = 0; ni < 3; ni++) {
            int col = ni * 8 + t4 * 2;
            float bb0 = b3s[col], bb1 = b3s[col + 1];
            h3f[(ew + g    ) * 68 + col    ] = fmaxf(a3[ni][0] + bb0, 0.f);
            h3f[(ew + g    ) * 68 + col + 1] = fmaxf(a3[ni][1] + bb1, 0.f);
            h3f[(ew + g + 8) * 68 + col    ] = fmaxf(a3[ni][2] + bb0, 0.f);
            h3f[(ew + g + 8) * 68 + col + 1] = fmaxf(a3[ni][3] + bb1, 0.f);
        }
    }
    __syncthreads();

    // ---- layer 4 + per-clause atomic accumulation ----
    if (tid < 128) {
        int ge = ebase + tid;
        if (ge < nE) {
            float w = b4s[0];
            #pragma unroll
            for (int j = 0; j < 20; j++) w += h3f[tid * 68 + j] * W4s[j];
            int cl = ejs[tid];
            atomicAdd(&g_sums[cl], w);
            atomicAdd(&g_cnts[cl], 1.0f);
        }
    }
}

// ----------------------------------------------------------------------------
__global__ void finalize_kernel(const int* __restrict__ edge_j,
                                float* __restrict__ out, int nE) {
    int e = blockIdx.x * blockDim.x + threadIdx.x;
    if (e < nE) {
        int j = edge_j[e];
        out[e] = g_sums[j] / fmaxf(g_cnts[j], 1.0f);
    }
}

// ----------------------------------------------------------------------------
extern "C" void kernel_launch(void* const* d_in, const int* in_sizes, int n_in,
                              void* d_out, int out_size)
{
    const float* l_embs = (const float*)d_in[0];
    const float* c_embs = (const float*)d_in[1];
    const int*   edge_i = (const int*)d_in[2];
    const int*   edge_j = (const int*)d_in[3];
    const float* W1     = (const float*)d_in[4];
    const float* b1     = (const float*)d_in[5];
    const float* W2     = (const float*)d_in[6];
    const float* b2     = (const float*)d_in[7];
    const float* W3     = (const float*)d_in[8];
    const float* b3     = (const float*)d_in[9];
    const float* W4     = (const float*)d_in[10];
    const float* b4     = (const float*)d_in[11];
    float* out = (float*)d_out;

    const int nL = in_sizes[0] / 384;   // 131072
    const int nC = in_sizes[1] / 384;   // 65536
    const int nE = in_sizes[2];         // 524288

    cudaFuncSetAttribute(edge_kernel,
                         cudaFuncAttributeMaxDynamicSharedMemorySize,
                         EK_SMEM_BYTES);

    prep_kernel<<<768, 256>>>(W1, W2, W3);
    gemm_LC<<<dim3((nL + nC) / 128, 2), 256>>>(l_embs, c_embs, b1, nL);
    zero_kernel<<<(nC + 255) / 256, 256>>>(nC);
    edge_kernel<<<(nE + 127) / 128, 256, EK_SMEM_BYTES>>>(
        edge_i, edge_j, b2, b3, W4, b4, nE);
    finalize_kernel<<<(nE + 255) / 256, 256>>>(edge_j, out, nE);
}

// round 17
// speedup vs baseline: 1.2294x; 1.0439x over previous
#include <cuda_runtime.h>
#include <cstdint>
#include <cstddef>

// ============================================================================
// MLP_SAT v7: v5 edge kernel (unchanged) + GEMM with cp.async double-buffered
// A AND W tiles (W staged per-block in smem again -> 4x less L2 B-traffic
// than v6.1's per-thread B LDG).
//   g_W2p: PERMUTED pack (c,s layout)  — edge_kernel layer 2
//   g_W3p: standard k-pair pack        — edge_kernel layer 3
// ============================================================================

#define NLITS 131072
#define NCLS  65536

__device__ float g_L[(size_t)NLITS * 256];
__device__ float g_C[(size_t)NCLS * 256];
__device__ float g_sums[NCLS];
__device__ float g_cnts[NCLS];
__device__ unsigned g_W2p[16384];   // [K<32][n<64][t4][th] permuted
__device__ unsigned g_W3p[1536];    // [k8<8][n<24][t4][th] standard

__device__ __forceinline__ unsigned f2tf(float x) {
    unsigned r;
    asm("cvt.rna.tf32.f32 %0, %1;" : "=r"(r) : "f"(x));
    return r;
}

__device__ __forceinline__ void mma_tf32(float* d, const unsigned* a, const unsigned* b) {
    asm volatile(
        "mma.sync.aligned.m16n8k8.row.col.f32.tf32.tf32.f32 "
        "{%0,%1,%2,%3}, {%4,%5,%6,%7}, {%8,%9}, {%0,%1,%2,%3};\n"
        : "+f"(d[0]), "+f"(d[1]), "+f"(d[2]), "+f"(d[3])
        : "r"(a[0]), "r"(a[1]), "r"(a[2]), "r"(a[3]), "r"(b[0]), "r"(b[1]));
}

__device__ __forceinline__ void cp_async16(unsigned smem_addr, const void* gptr) {
    asm volatile("cp.async.cg.shared.global [%0], [%1], 16;\n"
                 :: "r"(smem_addr), "l"(gptr));
}
__device__ __forceinline__ void cp_commit() {
    asm volatile("cp.async.commit_group;\n");
}
template<int N>
__device__ __forceinline__ void cp_wait() {
    asm volatile("cp.async.wait_group %0;\n" :: "n"(N));
}

// ----------------------------------------------------------------------------
// One-time weight repack (W2/W3 for the edge kernel only).
// ----------------------------------------------------------------------------
__global__ void prep_kernel(const float* __restrict__ W2,
                            const float* __restrict__ W3) {
    int idx = blockIdx.x * blockDim.x + threadIdx.x;
    if (idx < 16384) {                        // W2: permuted pack (edge v5)
        int k = idx >> 6, n = idx & 63;
        int c = k >> 4, r = k & 15;
        int t4 = r >> 2, s = (r >> 1) & 1, th = r & 1;
        int K = 2 * c + s;
        g_W2p[((K * 64 + n) * 4 + t4) * 2 + th] = f2tf(W2[k * 64 + n]);
    }
    if (idx < 1536) {                         // W3: standard, n padded to 24
        int th = idx & 1, t4 = (idx >> 1) & 3, r = idx >> 3;  // r = k8*24+n
        int k8 = r / 24, n = r % 24;
        int k = k8 * 8 + th * 4 + t4;
        g_W3p[idx] = f2tf((n < 20) ? W3[k * 20 + n] : 0.f);
    }
}

// ----------------------------------------------------------------------------
// Merged GEMM v7: BM=128, BN=128, BK=32; cp.async double-buffered A (128x32)
// and W (32x128) tiles; one __syncthreads per kt; f2tf at fragment read.
// Dynamic smem: 2 * (128*36 + 32*132) floats = 70,656 B -> 2 CTAs/SM.
// ----------------------------------------------------------------------------
#define GM_A_WORDS (128 * 36)
#define GM_W_WORDS (32 * 132)
#define GM_STAGE_WORDS (GM_A_WORDS + GM_W_WORDS)
#define GM_SMEM_BYTES (2 * GM_STAGE_WORDS * 4)

__global__ __launch_bounds__(256, 2) void gemm_LC(
    const float* __restrict__ l_embs, const float* __restrict__ c_embs,
    const float* __restrict__ W1, const float* __restrict__ b1, int nL)
{
    extern __shared__ float gsm[];
    // stage layout: [st][ A(128*36) | W(32*132) ]
    const int tid  = threadIdx.x;
    const int warp = tid >> 5, lane = tid & 31;
    const int g = lane >> 2, t4 = lane & 3;
    const int wm = warp & 3, wn = warp >> 2;
    const int rowBase = blockIdx.x * 128;
    const int colBase = blockIdx.y * 128;

    const bool isL = rowBase < nL;
    const float* __restrict__ A = isL ? l_embs + (size_t)rowBase * 384
                                      : c_embs + (size_t)(rowBase - nL) * 384;
    const float* __restrict__ W = isL ? W1 : W1 + (size_t)384 * 256;
    float* __restrict__ out = isL ? g_L + (size_t)rowBase * 256
                                  : g_C + (size_t)(rowBase - nL) * 256;

    // A cp.async coords: 4 slots (1024 float4); r = slot>>3, c4 = (slot&7)*4
    const int ra_[4] = { tid >> 3, (tid + 256) >> 3, (tid + 512) >> 3, (tid + 768) >> 3 };
    const int ca_    = (tid & 7) * 4;
    // W cp.async coords: 4 slots (1024 float4); r = slot>>5, c4 = (slot&31)*4
    const int rw_[4] = { tid >> 5, (tid + 256) >> 5, (tid + 512) >> 5, (tid + 768) >> 5 };
    const int cw_    = (tid & 31) * 4;

    float acc[2][8][4];
    #pragma unroll
    for (int mi = 0; mi < 2; mi++)
        #pragma unroll
        for (int ni = 0; ni < 8; ni++)
            #pragma unroll
            for (int q = 0; q < 4; q++) acc[mi][ni][q] = 0.f;

    // issue stage 0 (A + W in one group)
    {
        float* As0 = gsm;
        float* Ws0 = gsm + GM_A_WORDS;
        #pragma unroll
        for (int s = 0; s < 4; s++) {
            unsigned dA = (unsigned)__cvta_generic_to_shared(&As0[ra_[s] * 36 + ca_]);
            cp_async16(dA, &A[(size_t)ra_[s] * 384 + ca_]);
        }
        #pragma unroll
        for (int s = 0; s < 4; s++) {
            unsigned dW = (unsigned)__cvta_generic_to_shared(&Ws0[rw_[s] * 132 + cw_]);
            cp_async16(dW, &W[(size_t)rw_[s] * 256 + colBase + cw_]);
        }
        cp_commit();
    }

    for (int kt = 0; kt < 12; kt++) {
        const int st = kt & 1;
        float* As = gsm + st * GM_STAGE_WORDS;
        float* Ws = As + GM_A_WORDS;

        cp_wait<0>();      // stage kt fully landed
        __syncthreads();   // visible; all warps done with the other buffer

        if (kt < 11) {     // issue stage kt+1 (overlaps mma below)
            float* As1 = gsm + (st ^ 1) * GM_STAGE_WORDS;
            float* Ws1 = As1 + GM_A_WORDS;
            const int ko = (kt + 1) * 32;
            #pragma unroll
            for (int s = 0; s < 4; s++) {
                unsigned dA = (unsigned)__cvta_generic_to_shared(&As1[ra_[s] * 36 + ca_]);
                cp_async16(dA, &A[(size_t)ra_[s] * 384 + ko + ca_]);
            }
            #pragma unroll
            for (int s = 0; s < 4; s++) {
                unsigned dW = (unsigned)__cvta_generic_to_shared(&Ws1[rw_[s] * 132 + cw_]);
                cp_async16(dW, &W[(size_t)(ko + rw_[s]) * 256 + colBase + cw_]);
            }
            cp_commit();
        }

        #pragma unroll
        for (int k8 = 0; k8 < 4; k8++) {
            const int kc = k8 * 8;
            unsigned afr[2][4];
            #pragma unroll
            for (int mi = 0; mi < 2; mi++) {
                int rb = wm * 32 + mi * 16;
                afr[mi][0] = f2tf(As[(rb + g    ) * 36 + kc + t4    ]);
                afr[mi][1] = f2tf(As[(rb + g + 8) * 36 + kc + t4    ]);
                afr[mi][2] = f2tf(As[(rb + g    ) * 36 + kc + t4 + 4]);
                afr[mi][3] = f2tf(As[(rb + g + 8) * 36 + kc + t4 + 4]);
            }
            #pragma unroll
            for (int ni = 0; ni < 8; ni++) {
                int col = wn * 64 + ni * 8 + g;
                unsigned b[2];
                b[0] = f2tf(Ws[(kc + t4    ) * 132 + col]);
                b[1] = f2tf(Ws[(kc + t4 + 4) * 132 + col]);
                mma_tf32(acc[0][ni], afr[0], b);
                mma_tf32(acc[1][ni], afr[1], b);
            }
        }
    }

    #pragma unroll
    for (int mi = 0; mi < 2; mi++) {
        #pragma unroll
        for (int ni = 0; ni < 8; ni++) {
            int rr = wm * 32 + mi * 16 + g;
            int c0 = colBase + wn * 64 + ni * 8 + t4 * 2;
            float bb0 = isL ? b1[c0]     : 0.f;
            float bb1 = isL ? b1[c0 + 1] : 0.f;
            float2 v0 = {acc[mi][ni][0] + bb0, acc[mi][ni][1] + bb1};
            float2 v1 = {acc[mi][ni][2] + bb0, acc[mi][ni][3] + bb1};
            *(float2*)&out[(size_t)rr * 256 + c0] = v0;
            *(float2*)&out[(size_t)(rr + 8) * 256 + c0] = v1;
        }
    }
}

// ----------------------------------------------------------------------------
__global__ void zero_kernel(int n) {
    int i = blockIdx.x * blockDim.x + threadIdx.x;
    if (i < n) { g_sums[i] = 0.f; g_cnts[i] = 0.f; }
}

// ----------------------------------------------------------------------------
// Edge kernel v5 (unchanged): 128 edges/block, 8 warps x 16 edges, 4 CTAs/SM.
// ----------------------------------------------------------------------------
#define EK_SMEM_WORDS (128*68 + 64 + 24 + 20 + 4 + 256)
#define EK_SMEM_BYTES (EK_SMEM_WORDS * 4)

__global__ __launch_bounds__(256, 4) void edge_kernel(
    const int* __restrict__ edge_i, const int* __restrict__ edge_j,
    const float* __restrict__ b2, const float* __restrict__ b3,
    const float* __restrict__ W4, const float* __restrict__ b4,
    int nE)
{
    extern __shared__ unsigned smu[];
    unsigned* h2 = smu;                     // [128][68]
    float* b2s = (float*)(h2 + 128 * 68);   // 64
    float* b3s = b2s + 64;                  // 24
    float* W4s = b3s + 24;                  // 20
    float* b4s = W4s + 20;                  // 4
    int*   eis = (int*)(b4s + 4);           // 128
    int*   ejs = eis + 128;                 // 128
    float* h3f = (float*)h2;                // h3 overlays h2 rows (stride 68)

    const int tid  = threadIdx.x;
    const int warp = tid >> 5, lane = tid & 31;
    const int g = lane >> 2, t4 = lane & 3;
    const int ebase = blockIdx.x * 128;

    if (tid < 64) b2s[tid] = b2[tid];
    if (tid < 24) b3s[tid] = (tid < 20) ? b3[tid] : 0.f;
    if (tid < 20) W4s[tid] = W4[tid];
    if (tid == 0) b4s[0] = b4[0];
    if (tid < 128) {
        int ge = ebase + tid;
        eis[tid] = (ge < nE) ? edge_i[ge] : 0;
        ejs[tid] = (ge < nE) ? edge_j[ge] : 0;
    }
    __syncthreads();

    // ---- layer 2: warp-private, barrier-free ----
    const int ew = warp * 16;
    const size_t rL0 = (size_t)eis[ew + g    ] * 256;
    const size_t rL1 = (size_t)eis[ew + g + 8] * 256;
    const size_t rC0 = (size_t)ejs[ew + g    ] * 256;
    const size_t rC1 = (size_t)ejs[ew + g + 8] * 256;

    float acc[8][4];
    #pragma unroll
    for (int ni = 0; ni < 8; ni++)
        #pragma unroll
        for (int q = 0; q < 4; q++) acc[ni][q] = 0.f;

    for (int c = 0; c < 16; c++) {
        const int ko = c * 16 + t4 * 4;
        float4 l0 = *(const float4*)&g_L[rL0 + ko];
        float4 l1 = *(const float4*)&g_L[rL1 + ko];
        float4 c0 = *(const float4*)&g_C[rC0 + ko];
        float4 c1 = *(const float4*)&g_C[rC1 + ko];
        unsigned h0[4], h1[4];
        h0[0] = f2tf(fmaxf(l0.x + c0.x, 0.f));
        h0[1] = f2tf(fmaxf(l0.y + c0.y, 0.f));
        h0[2] = f2tf(fmaxf(l0.z + c0.z, 0.f));
        h0[3] = f2tf(fmaxf(l0.w + c0.w, 0.f));
        h1[0] = f2tf(fmaxf(l1.x + c1.x, 0.f));
        h1[1] = f2tf(fmaxf(l1.y + c1.y, 0.f));
        h1[2] = f2tf(fmaxf(l1.z + c1.z, 0.f));
        h1[3] = f2tf(fmaxf(l1.w + c1.w, 0.f));

        #pragma unroll
        for (int s = 0; s < 2; s++) {
            const int K = 2 * c + s;
            unsigned a[4] = {h0[2*s], h1[2*s], h0[2*s+1], h1[2*s+1]};
            #pragma unroll
            for (int ni = 0; ni < 8; ni++) {
                int col = ni * 8 + g;
                uint2 bp = *(const uint2*)&g_W2p[((K * 64 + col) * 4 + t4) * 2];
                unsigned b[2] = {bp.x, bp.y};
                mma_tf32(acc[ni], a, b);
            }
        }
    }

    // ---- layer-2 epilogue ----
    #pragma unroll
    for (int ni = 0; ni < 8; ni++) {
        int col = ni * 8 + t4 * 2;
        float bb0 = b2s[col], bb1 = b2s[col + 1];
        h2[(ew + g    ) * 68 + col    ] = f2tf(fmaxf(acc[ni][0] + bb0, 0.f));
        h2[(ew + g    ) * 68 + col + 1] = f2tf(fmaxf(acc[ni][1] + bb1, 0.f));
        h2[(ew + g + 8) * 68 + col    ] = f2tf(fmaxf(acc[ni][2] + bb0, 0.f));
        h2[(ew + g + 8) * 68 + col + 1] = f2tf(fmaxf(acc[ni][3] + bb1, 0.f));
    }
    __syncwarp();

    // ---- layer 3 ----
    {
        float a3[3][4];
        #pragma unroll
        for (int ni = 0; ni < 3; ni++)
            #pragma unroll
            for (int q = 0; q < 4; q++) a3[ni][q] = 0.f;

        #pragma unroll
        for (int k8 = 0; k8 < 8; k8++) {
            const int kc = k8 * 8;
            unsigned a[4];
            a[0] = h2[(ew + g    ) * 68 + kc + t4    ];
            a[1] = h2[(ew + g + 8) * 68 + kc + t4    ];
            a[2] = h2[(ew + g    ) * 68 + kc + t4 + 4];
            a[3] = h2[(ew + g + 8) * 68 + kc + t4 + 4];
            #pragma unroll
            for (int ni = 0; ni < 3; ni++) {
                int col = ni * 8 + g;
                uint2 bp = *(const uint2*)&g_W3p[((k8 * 24 + col) * 4 + t4) * 2];
                unsigned b[2] = {bp.x, bp.y};
                mma_tf32(a3[ni], a, b);
            }
        }
        #pragma unroll
        for (int ni = 0; ni < 3; ni++) {
            int col = ni * 8 + t4 * 2;
            float bb0 = b3s[col], bb1 = b3s[col + 1];
            h3f[(ew + g    ) * 68 + col    ] = fmaxf(a3[ni][0] + bb0, 0.f);
            h3f[(ew + g    ) * 68 + col + 1] = fmaxf(a3[ni][1] + bb1, 0.f);
            h3f[(ew + g + 8) * 68 + col    ] = fmaxf(a3[ni][2] + bb0, 0.f);
            h3f[(ew + g + 8) * 68 + col + 1] = fmaxf(a3[ni][3] + bb1, 0.f);
        }
    }
    __syncthreads();

    // ---- layer 4 + per-clause atomic accumulation ----
    if (tid < 128) {
        int ge = ebase + tid;
        if (ge < nE) {
            float w = b4s[0];
            #pragma unroll
            for (int j = 0; j < 20; j++) w += h3f[tid * 68 + j] * W4s[j];
            int cl = ejs[tid];
            atomicAdd(&g_sums[cl], w);
            atomicAdd(&g_cnts[cl], 1.0f);
        }
    }
}

// ----------------------------------------------------------------------------
__global__ void finalize_kernel(const int* __restrict__ edge_j,
                                float* __restrict__ out, int nE) {
    int e = blockIdx.x * blockDim.x + threadIdx.x;
    if (e < nE) {
        int j = edge_j[e];
        out[e] = g_sums[j] / fmaxf(g_cnts[j], 1.0f);
    }
}

// ----------------------------------------------------------------------------
extern "C" void kernel_launch(void* const* d_in, const int* in_sizes, int n_in,
                              void* d_out, int out_size)
{
    const float* l_embs = (const float*)d_in[0];
    const float* c_embs = (const float*)d_in[1];
    const int*   edge_i = (const int*)d_in[2];
    const int*   edge_j = (const int*)d_in[3];
    const float* W1     = (const float*)d_in[4];
    const float* b1     = (const float*)d_in[5];
    const float* W2     = (const float*)d_in[6];
    const float* b2     = (const float*)d_in[7];
    const float* W3     = (const float*)d_in[8];
    const float* b3     = (const float*)d_in[9];
    const float* W4     = (const float*)d_in[10];
    const float* b4     = (const float*)d_in[11];
    float* out = (float*)d_out;

    const int nL = in_sizes[0] / 384;   // 131072
    const int nC = in_sizes[1] / 384;   // 65536
    const int nE = in_sizes[2];         // 524288

    cudaFuncSetAttribute(gemm_LC,
                         cudaFuncAttributeMaxDynamicSharedMemorySize,
                         GM_SMEM_BYTES);
    cudaFuncSetAttribute(edge_kernel,
                         cudaFuncAttributeMaxDynamicSharedMemorySize,
                         EK_SMEM_BYTES);

    prep_kernel<<<64, 256>>>(W2, W3);
    gemm_LC<<<dim3((nL + nC) / 128, 2), 256, GM_SMEM_BYTES>>>(
        l_embs, c_embs, W1, b1, nL);
    zero_kernel<<<(nC + 255) / 256, 256>>>(nC);
    edge_kernel<<<(nE + 127) / 128, 256, EK_SMEM_BYTES>>>(
        edge_i, edge_j, b2, b3, W4, b4, nE);
    finalize_kernel<<<(nE + 255) / 256, 256>>>(edge_j, out, nE);
}